// round 9
// baseline (speedup 1.0000x reference)
#include <cuda_runtime.h>
#include <cstdint>

// SpatialPool: fm [B=16, C=512, H=38, W=38] f32 (NCHW)
//   -> out [B, H*W, 9*C] f32, out[b, h*W+w, (di*3+dj)*C + c]
//      = fm[b, c, clamp(h+di-1), clamp(w+dj-1)]  (replicate pad)
//
// R9: one CTA owns ALL 512 channels of a (10-wide x 1 row) strip, so each
// 2KB output chunk (w,n) is written contiguously by a single warp
// (4 independent LDS.128 + 4 independent STG.128.cs) -> one DRAM page
// open per chunk instead of four, and 4x per-warp store MLP.
// Load phase: coalesced cp.async into float4-XOR-swizzled smem with
// incremental (c,p) indexing (no divisions in the loop body).

namespace {
constexpr int HH   = 38;
constexpr int C    = 512;
constexpr int NB   = 9;
constexpr int WTX  = 10;          // w positions per CTA (4 quarters: 10,10,10,8)
constexpr int LW   = WTX + 2;     // 12 local cols incl. halo
constexpr int NPOS = 3 * LW;      // 36 smem positions
constexpr int THREADS = 512;
constexpr int HW   = HH * HH;     // 1444
constexpr int RS4  = NB * C / 4;  // 1152 float4 per (b,y,w)
constexpr int SMEM_BYTES = NPOS * C * 4;   // 73,728 B
constexpr int LOAD_ITERS = NPOS * C / THREADS;   // 36
constexpr int PSTEP = (THREADS % NPOS);          // 8
constexpr int CSTEP = (THREADS / NPOS);          // 14
}

__device__ __forceinline__ void cp_async4(float* smem_dst, const float* gsrc) {
    uint32_t sa = (uint32_t)__cvta_generic_to_shared(smem_dst);
    asm volatile("cp.async.ca.shared.global [%0], [%1], 4;\n"
                 :: "r"(sa), "l"(gsrc) : "memory");
}

__global__ __launch_bounds__(THREADS, 3)
void spatialpool_kernel(const float* __restrict__ fm, float* __restrict__ out) {
    // logical (pos, c) at smP[pos*512 + 4*((c>>2)^(pos&31)) + (c&3)]
    extern __shared__ float smP[];

    const int lane = threadIdx.x & 31;
    const int wid  = threadIdx.x >> 5;

    const int wq = blockIdx.x;          // w quarter 0..3
    const int w0 = wq * WTX;
    const int y  = blockIdx.y;
    const int b  = blockIdx.z;

    const float* __restrict__ fb = fm + (size_t)b * C * HW;

    // ---- Load: linear sweep of idx = c*36 + p with incremental (c,p).
    // Lanes hold consecutive idx -> consecutive p -> coalesced cp.async. ----
    {
        int c = threadIdx.x / NPOS;          // one div, outside loop
        int p = threadIdx.x - c * NPOS;
        #pragma unroll 4
        for (int it = 0; it < LOAD_ITERS; ++it) {
            int r  = (p >= 2 * LW) ? 2 : ((p >= LW) ? 1 : 0);
            int l  = p - r * LW;
            int yl = min(max(y - 1 + r, 0), HH - 1);
            int xg = min(max(w0 - 1 + l, 0), HH - 1);
            int sw = (p << 9) + ((((c >> 2) ^ (p & 31)) << 2) | (c & 3));
            cp_async4(&smP[sw], &fb[c * HW + yl * HH + xg]);
            // advance idx by THREADS: p += 8 (mod 36), c += 14 (+carry)
            p += PSTEP; c += CSTEP;
            if (p >= NPOS) { p -= NPOS; c += 1; }
        }
    }
    asm volatile("cp.async.wait_all;\n" ::: "memory");
    __syncthreads();

    // ---- Write: warp-per-chunk, chunk = (wl, n) = 512 floats = 2KB,
    // written contiguously: 4 independent LDS.128 + 4 STG.128.cs. ----
    float4* __restrict__ out4 = (float4*)out;
    const size_t base4 =
        ((size_t)b * HW + (size_t)y * HH + w0) * (size_t)RS4 + lane;

    for (int tch = wid; tch < WTX * NB; tch += THREADS / 32) {
        int wl = tch / NB;
        int n  = tch - wl * NB;
        if (w0 + wl >= HH) continue;            // wq=3 tail (w=38,39)
        int di = (n >= 6) ? 2 : ((n >= 3) ? 1 : 0);
        int pos = LW * di + wl + n - 3 * di;    // di*12 + wl + dj

        const float* __restrict__ sp = &smP[pos << 9];
        const int key = pos & 31;
        float4* __restrict__ o =
            &out4[base4 + (size_t)wl * RS4 + n * (C / 4)];

        #pragma unroll
        for (int k = 0; k < 4; ++k) {
            const float4 v = *(const float4*)
                &sp[((lane + 32 * k) ^ key) << 2];
            __stcs(&o[32 * k], v);
        }
    }
}

extern "C" void kernel_launch(void* const* d_in, const int* in_sizes, int n_in,
                              void* d_out, int out_size) {
    const float* fm = (const float*)d_in[0];
    float* out = (float*)d_out;
    (void)in_sizes; (void)n_in; (void)out_size;

    cudaFuncSetAttribute(spatialpool_kernel,
                         cudaFuncAttributeMaxDynamicSharedMemorySize,
                         SMEM_BYTES);

    dim3 grid(4, HH, 16);   // (4, 38, 16) = 2432 CTAs
    spatialpool_kernel<<<grid, THREADS, SMEM_BYTES>>>(fm, out);
}

// round 10
// speedup vs baseline: 1.3708x; 1.3708x over previous
#include <cuda_runtime.h>
#include <cstdint>

// SpatialPool: fm [B=16, C=512, H=38, W=38] f32 (NCHW)
//   -> out [B, H*W, 9*C] f32, out[b, h*W+w, (di*3+dj)*C + c]
//      = fm[b, c, clamp(h+di-1), clamp(w+dj-1)]  (replicate pad)
//
// R10 = R7 with exactly ONE change: write phase iterates in ascending
// output-address order, each warp owning a contiguous ~21-chunk range
// (~10.9KB monotone store stream per warp) instead of n-major strided.
// Load phase / smem swizzle / occupancy identical to R7 (best: 79.6us).

namespace {
constexpr int HH   = 38;
constexpr int C    = 512;
constexpr int CSUB = 128;        // channels per CTA
constexpr int NCG  = C / CSUB;   // 4
constexpr int NB   = 9;
constexpr int WT   = 19;         // w positions per CTA
constexpr int LW   = WT + 2;     // 21 local cols incl. halo
constexpr int NY   = 2;          // output rows per CTA
constexpr int NR   = NY + 2;     // 4 loaded rows incl. halo
constexpr int NPOS = NR * LW;    // 84 smem positions
constexpr int THREADS = 512;
constexpr int NWARP = THREADS / 32;
constexpr int HW   = HH * HH;    // 1444
constexpr int RS4  = NB * C / 4; // 1152 float4 per (b,y,w)
constexpr int YS4  = HH * RS4;   // float4 stride for y+1
constexpr int CHUNKS = NY * WT * NB;   // 342 chunks per CTA
}

__device__ __forceinline__ void cp_async4(float* smem_dst, const float* gsrc) {
    uint32_t sa = (uint32_t)__cvta_generic_to_shared(smem_dst);
    asm volatile("cp.async.ca.shared.global [%0], [%1], 4;\n"
                 :: "r"(sa), "l"(gsrc) : "memory");
}

__global__ __launch_bounds__(THREADS, 4)
void spatialpool_kernel(const float* __restrict__ fm, float* __restrict__ out) {
    // logical (pos, c) at smP[pos*128 + 4*((c>>2)^(pos&31)) + (c&3)]
    __shared__ float smP[NPOS * CSUB];   // 43,008 B

    const int lane = threadIdx.x & 31;
    const int wid  = threadIdx.x >> 5;

    const int wh = blockIdx.x & 1;
    const int cg = blockIdx.x >> 1;        // channel group 0..3
    const int w0 = wh * WT;
    const int y0 = blockIdx.y * NY;        // first output row
    const int b  = blockIdx.z;

    const float* __restrict__ fb =
        fm + ((size_t)b * C + (size_t)cg * CSUB) * HW;

    // ---- Load (identical to R7): thread owns p = lane + 32k, sweeps
    // c = wid + 16m; channel stride folded into LDGSTS immediates. ----
    {
        const float* __restrict__ fc = fb + (size_t)wid * HW;  // c0 = wid
        const int c3  = wid & 3;
        const int cq0 = wid >> 2;
        #pragma unroll
        for (int k = 0; k < 3; ++k) {
            int p = lane + 32 * k;
            if (k == 2 && p >= NPOS) break;
            int r  = p / LW;
            int l  = p - r * LW;
            int yl = min(max(y0 - 1 + r, 0), HH - 1);
            int xg = min(max(w0 - 1 + l, 0), HH - 1);
            const float* __restrict__ g = fc + yl * HH + xg;
            const int swk = (p << 7) + c3;
            #pragma unroll
            for (int m = 0; m < 8; ++m) {
                int sw = swk + (((cq0 + 4 * m) ^ lane) << 2);
                cp_async4(&smP[sw], g + m * 16 * HW);
            }
        }
    }
    asm volatile("cp.async.wait_all;\n" ::: "memory");
    __syncthreads();

    // ---- Write: address-ordered, warp owns a CONTIGUOUS chunk range.
    // t = ((o*19 + wl)*9 + n) ascends with output address; each warp
    // streams ~21 consecutive 512B chunks (one LDS.128 + one STG.128.cs
    // per chunk) -> ~10.9KB monotone store stream per warp. ----
    float4* __restrict__ out4 = (float4*)out;
    const size_t rowbase =
        ((size_t)b * HW + (size_t)y0 * HH + w0) * (size_t)RS4
        + (size_t)cg * (CSUB / 4) + lane;

    const int lo = (CHUNKS * wid) / NWARP;
    const int hi = (CHUNKS * (wid + 1)) / NWARP;

    #pragma unroll 2
    for (int t = lo; t < hi; ++t) {
        int o  = (t >= WT * NB) ? 1 : 0;       // t / 171
        int rm = t - o * (WT * NB);
        int wl = rm / NB;                      // magic-mul
        int n  = rm - wl * NB;
        int di = (n >= 6) ? 2 : ((n >= 3) ? 1 : 0);
        int pos = (o + di) * LW + wl + (n - 3 * di);

        const float4 v = *(const float4*)
            &smP[(pos << 7) + ((lane ^ (pos & 31)) << 2)];
        __stcs(&out4[rowbase + (size_t)o * YS4
                     + (size_t)wl * RS4 + n * (C / 4)], v);
    }
}

extern "C" void kernel_launch(void* const* d_in, const int* in_sizes, int n_in,
                              void* d_out, int out_size) {
    const float* fm = (const float*)d_in[0];
    float* out = (float*)d_out;
    (void)in_sizes; (void)n_in; (void)out_size;

    dim3 grid(2 * NCG, HH / NY, 16);   // (8, 19, 16) = 2432 CTAs
    spatialpool_kernel<<<grid, THREADS>>>(fm, out);
}